// round 2
// baseline (speedup 1.0000x reference)
#include <cuda_runtime.h>
#include <math.h>

// Problem constants
#define NSDE_T 500
#define NSDE_B 4096
// 8 threads per batch row, 32 rows per CTA, 128 CTAs

__global__ __launch_bounds__(256, 1)
void nsde_kernel(const float* __restrict__ y0,
                 const float* __restrict__ noise,
                 const float* __restrict__ dw1, const float* __restrict__ db1,
                 const float* __restrict__ dw2, const float* __restrict__ db2,
                 const float* __restrict__ gw1, const float* __restrict__ gb1,
                 const float* __restrict__ gw2, const float* __restrict__ gb2,
                 float* __restrict__ out)
{
    extern __shared__ float sm[];
    // SMEM partition (floats):
    float* w1d = sm;              // [k][j] 32*128
    float* w1g = w1d + 4096;      // [k][j]
    float* w2d = w1g + 4096;      // [j][i] 128*32
    float* w2g = w2d + 4096;
    float* b1d = w2g + 4096;      // 128
    float* b1g = b1d + 128;
    float* b2d = b1g + 128;       // 32
    float* b2g = b2d + 32;
    float* hs  = b2g + 32;        // per-row hidden: 32 rows * 128
    float* ys  = hs  + 4096;      // per-row state: 32 rows * 33 (padded)

    const int tid = threadIdx.x;
    const int lr  = tid >> 3;          // local row 0..31
    const int jg  = tid & 7;           // group lane 0..7
    const int row = blockIdx.x * 32 + lr;
    const int swz = 4 * (lr & 3);      // per-warp-row xor swizzle for hs

    // ---- Stage weights into SMEM (transposed for conflict-free inner loops) ----
    for (int w = tid; w < 4096; w += 256) {
        int k = w >> 7, j = w & 127;         // w1s[k*128+j] = W1[j][k]
        w1d[w] = dw1[j * 32 + k];
        w1g[w] = gw1[j * 32 + k];
        int j2 = w >> 5, i2 = w & 31;        // w2s[j*32+i] = W2[i][j]
        w2d[w] = dw2[i2 * 128 + j2];
        w2g[w] = gw2[i2 * 128 + j2];
    }
    if (tid < 128) { b1d[tid] = db1[tid]; b1g[tid] = gb1[tid]; }
    if (tid < 32)  { b2d[tid] = db2[tid]; b2g[tid] = gb2[tid]; }

    // ---- y0 init: write out[0] and seed ys ----
    float4 yv = *(const float4*)(y0 + (size_t)row * 32 + 4 * jg);
    *(float4*)(out + (size_t)row * 32 + 4 * jg) = yv;
    ys[lr * 33 + 4 * jg + 0] = yv.x;
    ys[lr * 33 + 4 * jg + 1] = yv.y;
    ys[lr * 33 + 4 * jg + 2] = yv.z;
    ys[lr * 33 + 4 * jg + 3] = yv.w;
    __syncthreads();

    const float dt   = 0.01f;
    const float sqdt = __fsqrt_rn(dt);   // IEEE, matches jnp.sqrt(float32(0.01))

    float f0 = 0.f, f1 = 0.f, f2 = 0.f, f3 = 0.f;
    float g0 = 0.f, g1 = 0.f, g2 = 0.f, g3 = 0.f;

    for (int s = 0; s < NSDE_T; s++) {
        // issue noise load early; consumed at end of step (latency hidden)
        const float4 nv =
            *(const float4*)(noise + ((size_t)s * NSDE_B + row) * 32 + 4 * jg);

        #pragma unroll
        for (int m = 0; m < 2; m++) {
            const float* w1 = m ? w1g : w1d;
            const float* w2 = m ? w2g : w2d;
            const float* b1 = m ? b1g : b1d;
            const float* b2 = m ? b2g : b2d;

            // ---- GEMM1: h[j] = b1[j] + sum_k W1[j][k] * y[k], j in thread's 16 ----
            float h[16];
            #pragma unroll
            for (int c = 0; c < 4; c++) {
                float4 bv = *(const float4*)(b1 + 32 * c + 4 * jg);
                h[4 * c + 0] = bv.x; h[4 * c + 1] = bv.y;
                h[4 * c + 2] = bv.z; h[4 * c + 3] = bv.w;
            }
            #pragma unroll 4
            for (int k = 0; k < 32; k++) {
                float yk = ys[lr * 33 + k];
                #pragma unroll
                for (int c = 0; c < 4; c++) {
                    float4 wv = *(const float4*)(w1 + k * 128 + 32 * c + 4 * jg);
                    h[4 * c + 0] = fmaf(wv.x, yk, h[4 * c + 0]);
                    h[4 * c + 1] = fmaf(wv.y, yk, h[4 * c + 1]);
                    h[4 * c + 2] = fmaf(wv.z, yk, h[4 * c + 2]);
                    h[4 * c + 3] = fmaf(wv.w, yk, h[4 * c + 3]);
                }
            }
            #pragma unroll
            for (int q = 0; q < 16; q++) h[q] = fmaxf(h[q], 0.0f);

            // protect hs against previous GEMM2 readers, then publish h
            __syncwarp();
            #pragma unroll
            for (int c = 0; c < 4; c++) {
                float4 hv = make_float4(h[4 * c + 0], h[4 * c + 1],
                                        h[4 * c + 2], h[4 * c + 3]);
                *(float4*)(hs + lr * 128 + ((32 * c + 4 * jg) ^ swz)) = hv;
            }
            __syncwarp();

            // ---- GEMM2: out[i] = b2[i] + sum_j W2[i][j]*h[j], i in 4jg..4jg+3 ----
            float4 bv2 = *(const float4*)(b2 + 4 * jg);
            float a0 = bv2.x, a1 = bv2.y, a2 = bv2.z, a3 = bv2.w;
            #pragma unroll 4
            for (int jb = 0; jb < 32; jb++) {
                float4 hv = *(const float4*)(hs + lr * 128 + ((4 * jb) ^ swz));
                const float* wp = w2 + (4 * jb) * 32 + 4 * jg;
                float4 wa = *(const float4*)(wp);
                float4 wb = *(const float4*)(wp + 32);
                float4 wc = *(const float4*)(wp + 64);
                float4 wd = *(const float4*)(wp + 96);
                a0 = fmaf(wa.x, hv.x, a0); a1 = fmaf(wa.y, hv.x, a1);
                a2 = fmaf(wa.z, hv.x, a2); a3 = fmaf(wa.w, hv.x, a3);
                a0 = fmaf(wb.x, hv.y, a0); a1 = fmaf(wb.y, hv.y, a1);
                a2 = fmaf(wb.z, hv.y, a2); a3 = fmaf(wb.w, hv.y, a3);
                a0 = fmaf(wc.x, hv.z, a0); a1 = fmaf(wc.y, hv.z, a1);
                a2 = fmaf(wc.z, hv.z, a2); a3 = fmaf(wc.w, hv.z, a3);
                a0 = fmaf(wd.x, hv.w, a0); a1 = fmaf(wd.y, hv.w, a1);
                a2 = fmaf(wd.z, hv.w, a2); a3 = fmaf(wd.w, hv.w, a3);
            }
            if (m == 0) { f0 = a0; f1 = a1; f2 = a2; f3 = a3; }
            else        { g0 = a0; g1 = a1; g2 = a2; g3 = a3; }
        }

        // ---- Euler–Maruyama update: y += f*dt + g*(sqrt(dt)*n) ----
        float yo0 = ys[lr * 33 + 4 * jg + 0];
        float yo1 = ys[lr * 33 + 4 * jg + 1];
        float yo2 = ys[lr * 33 + 4 * jg + 2];
        float yo3 = ys[lr * 33 + 4 * jg + 3];
        float z0 = fmaf(g0, sqdt * nv.x, fmaf(f0, dt, yo0));
        float z1 = fmaf(g1, sqdt * nv.y, fmaf(f1, dt, yo1));
        float z2 = fmaf(g2, sqdt * nv.z, fmaf(f2, dt, yo2));
        float z3 = fmaf(g3, sqdt * nv.w, fmaf(f3, dt, yo3));

        *(float4*)(out + ((size_t)(s + 1) * NSDE_B + row) * 32 + 4 * jg) =
            make_float4(z0, z1, z2, z3);

        // all lanes must be done reading old ys before any lane rewrites it
        __syncwarp();
        ys[lr * 33 + 4 * jg + 0] = z0;
        ys[lr * 33 + 4 * jg + 1] = z1;
        ys[lr * 33 + 4 * jg + 2] = z2;
        ys[lr * 33 + 4 * jg + 3] = z3;
        __syncwarp();
    }
}

extern "C" void kernel_launch(void* const* d_in, const int* in_sizes, int n_in,
                              void* d_out, int out_size)
{
    // metadata order: ts, y0, noise, drift_w1, drift_b1, drift_w2, drift_b2,
    //                 diff_w1, diff_b1, diff_w2, diff_b2
    const float* y0    = (const float*)d_in[1];
    const float* noise = (const float*)d_in[2];
    const float* dw1   = (const float*)d_in[3];
    const float* db1   = (const float*)d_in[4];
    const float* dw2   = (const float*)d_in[5];
    const float* db2   = (const float*)d_in[6];
    const float* gw1   = (const float*)d_in[7];
    const float* gb1   = (const float*)d_in[8];
    const float* gw2   = (const float*)d_in[9];
    const float* gb2   = (const float*)d_in[10];
    float* out = (float*)d_out;

    const size_t smem_bytes = 21856 * sizeof(float);  // 87,424 B
    cudaFuncSetAttribute(nsde_kernel,
                         cudaFuncAttributeMaxDynamicSharedMemorySize,
                         (int)smem_bytes);
    nsde_kernel<<<128, 256, smem_bytes>>>(y0, noise, dw1, db1, dw2, db2,
                                          gw1, gb1, gw2, gb2, out);
}

// round 4
// speedup vs baseline: 1.6979x; 1.6979x over previous
#include <cuda_runtime.h>

#define T_STEPS 500
#define NB 4096
#define RPC 16          // rows per CTA
#define NCTA (NB / RPC) // 256

// SMEM layout (floats):
//  w1s [2][128][36]  (pad 36: stride-36 float4 reads are phase-conflict-free)
//  w2s [2][32][132]
//  hsm [2][16][128]
//  pp  [2][4][16][32]
//  ys  [16][32]
//  b2s [2][32]
#define W1S_F (2*128*36)
#define W2S_F (2*32*132)
#define HSM_F (2*16*128)
#define PP_F  (2*4*16*32)
#define YS_F  (16*32)
#define B2S_F (2*32)
#define SMEM_F (W1S_F + W2S_F + HSM_F + PP_F + YS_F + B2S_F)

__global__ __launch_bounds__(256, 2)
void nsde2(const float* __restrict__ y0, const float* __restrict__ noise,
           const float* __restrict__ dw1, const float* __restrict__ db1,
           const float* __restrict__ dw2, const float* __restrict__ db2,
           const float* __restrict__ gw1, const float* __restrict__ gb1,
           const float* __restrict__ gw2, const float* __restrict__ gb2,
           float* __restrict__ out)
{
    extern __shared__ float sm[];
    float* w1s = sm;
    float* w2s = w1s + W1S_F;
    float* hsm = w2s + W2S_F;
    float* pp  = hsm + HSM_F;
    float* ys  = pp  + PP_F;
    float* b2s = ys  + YS_F;

    const int tid  = threadIdx.x;
    const int lane = tid & 31;
    const int wid  = tid >> 5;
    const int m    = wid >> 2;   // 0 = drift, 1 = diffusion
    const int q    = wid & 3;    // hidden/j quarter
    const int base = blockIdx.x * RPC;

    // ---- stage weights (one time) ----
    {
        const float* W1m[2] = {dw1, gw1};
        const float* W2m[2] = {dw2, gw2};
        for (int idx = tid; idx < 2 * 128 * 32; idx += 256) {
            int mm = idx >> 12, rest = idx & 4095;
            int j = rest >> 5, k = rest & 31;
            w1s[(mm * 128 + j) * 36 + k] = W1m[mm][j * 32 + k];
            int i2 = rest >> 7, j2 = rest & 127;
            w2s[(mm * 32 + i2) * 132 + j2] = W2m[mm][i2 * 128 + j2];
        }
    }
    if (tid < 64) b2s[tid] = (tid < 32) ? db2[tid] : gb2[tid - 32];
    const float b1r = (m ? gb1 : db1)[q * 32 + lane];

    // ---- init ys + out[0] ----
    for (int v = tid; v < RPC * 32; v += 256) {
        int r = v >> 5, i = v & 31;
        float val = y0[(size_t)(base + r) * 32 + i];
        ys[r * 32 + i] = val;
        out[(size_t)(base + r) * 32 + i] = val;
    }
    __syncthreads();

    const float* w1row = w1s + (m * 128 + q * 32 + lane) * 36;   // W1[j][k], j = 32q+lane
    const float* w2row = w2s + (m * 32 + lane) * 132 + q * 32;   // W2[i=lane][32q + ...]
    float*       hwr   = hsm + m * 2048 + q * 32 + lane;         // write h[r*128]
    const float* hrd   = hsm + m * 2048 + q * 32;                // read  h[r*128 + j4*4]
    float*       ppw   = pp + ((m * 4 + q) * 16) * 32 + lane;    // write partials

    const float dt   = 0.01f;
    const float sqdt = __fsqrt_rn(dt);

    for (int s = 0; s < T_STEPS; s++) {
        // prefetch this step's noise (consumed ~1500 instrs later)
        const size_t nbase = ((size_t)s * NB + base) * 32;
        const float n0 = noise[nbase + tid];
        const float n1 = noise[nbase + tid + 256];

        // ---- GEMM1: h[j] = relu(b1[j] + sum_k W1[j][k] y[r][k]) for 16 rows ----
        float h[RPC];
        #pragma unroll
        for (int r = 0; r < RPC; r++) h[r] = b1r;
        #pragma unroll 4
        for (int k4 = 0; k4 < 8; k4++) {
            float4 wv = *(const float4*)(w1row + k4 * 4);
            #pragma unroll
            for (int r = 0; r < RPC; r++) {
                float4 yv = *(const float4*)(ys + r * 32 + k4 * 4);  // broadcast
                h[r] = fmaf(wv.w, yv.w, fmaf(wv.z, yv.z,
                        fmaf(wv.y, yv.y, fmaf(wv.x, yv.x, h[r]))));
            }
        }
        #pragma unroll
        for (int r = 0; r < RPC; r++) hwr[r * 128] = fmaxf(h[r], 0.0f);
        __syncthreads();

        // ---- GEMM2: partial[i] = sum_{j in quarter} W2[i][j] h[r][j] ----
        float acc[RPC];
        #pragma unroll
        for (int r = 0; r < RPC; r++) acc[r] = 0.0f;
        #pragma unroll 4
        for (int j4 = 0; j4 < 8; j4++) {
            float4 wv = *(const float4*)(w2row + j4 * 4);
            #pragma unroll
            for (int r = 0; r < RPC; r++) {
                float4 hv = *(const float4*)(hrd + r * 128 + j4 * 4);  // broadcast
                acc[r] = fmaf(wv.w, hv.w, fmaf(wv.z, hv.z,
                          fmaf(wv.y, hv.y, fmaf(wv.x, hv.x, acc[r]))));
            }
        }
        #pragma unroll
        for (int r = 0; r < RPC; r++) ppw[r * 32] = acc[r];
        __syncthreads();

        // ---- reduce quarters + Euler–Maruyama update (2 elements/thread) ----
        float z[2];
        const float nn[2] = {n0, n1};
        #pragma unroll
        for (int vv = 0; vv < 2; vv++) {
            int v = tid + vv * 256;
            int r = v >> 5, i = v & 31;
            const float* p0 = pp + r * 32 + i;
            float f = p0[0] + p0[512] + p0[1024] + p0[1536] + b2s[i];
            const float* p1 = p0 + 2048;
            float g = p1[0] + p1[512] + p1[1024] + p1[1536] + b2s[32 + i];
            float y = ys[r * 32 + i];
            z[vv] = fmaf(g, sqdt * nn[vv], fmaf(f, dt, y));
            out[((size_t)(s + 1) * NB + base + r) * 32 + i] = z[vv];
        }
        // each thread rewrites exactly the ys element it read — no race
        #pragma unroll
        for (int vv = 0; vv < 2; vv++) {
            int v = tid + vv * 256;
            ys[(v >> 5) * 32 + (v & 31)] = z[vv];
        }
        __syncthreads();
    }
}

extern "C" void kernel_launch(void* const* d_in, const int* in_sizes, int n_in,
                              void* d_out, int out_size)
{
    // metadata order: ts, y0, noise, drift_w1, drift_b1, drift_w2, drift_b2,
    //                 diff_w1, diff_b1, diff_w2, diff_b2
    const float* y0    = (const float*)d_in[1];
    const float* noise = (const float*)d_in[2];
    const float* dw1   = (const float*)d_in[3];
    const float* db1   = (const float*)d_in[4];
    const float* dw2   = (const float*)d_in[5];
    const float* db2   = (const float*)d_in[6];
    const float* gw1   = (const float*)d_in[7];
    const float* gb1   = (const float*)d_in[8];
    const float* gw2   = (const float*)d_in[9];
    const float* gb2   = (const float*)d_in[10];
    float* out = (float*)d_out;

    const size_t smem_bytes = SMEM_F * sizeof(float);  // 105,728 B
    cudaFuncSetAttribute(nsde2,
                         cudaFuncAttributeMaxDynamicSharedMemorySize,
                         (int)smem_bytes);
    nsde2<<<NCTA, 256, smem_bytes>>>(y0, noise, dw1, db1, dw2, db2,
                                     gw1, gb1, gw2, gb2, out);
}

// round 7
// speedup vs baseline: 1.8655x; 1.0987x over previous
#include <cuda_runtime.h>

#define T_STEPS 500
#define NB 4096
#define RPC 32          // rows per CTA
#define NCTA (NB / RPC) // 128

typedef unsigned long long ull;

// packed fp32x2 FMA (sm_103a FFMA2): d.lo = a.lo*b.lo + c.lo, d.hi likewise
__device__ __forceinline__ ull ffma2(ull a, ull b, ull c) {
    ull d;
    asm("fma.rn.f32x2 %0, %1, %2, %3;" : "=l"(d) : "l"(a), "l"(b), "l"(c));
    return d;
}
__device__ __forceinline__ float pair_sum(ull p) {
    return __uint_as_float((unsigned)p) + __uint_as_float((unsigned)(p >> 32));
}

// SMEM (floats): hsm[2][32][128], pp[2][4][32][32], ys[32][32], b2s[64]
#define HSM_F (2*32*128)
#define PP_F  (2*4*32*32)
#define YS_F  (32*32)
#define B2S_F 64
#define SMEM_F (HSM_F + PP_F + YS_F + B2S_F)

__global__ __launch_bounds__(256, 1)
void nsde3(const float* __restrict__ y0, const float* __restrict__ noise,
           const float* __restrict__ dw1, const float* __restrict__ db1,
           const float* __restrict__ dw2, const float* __restrict__ db2,
           const float* __restrict__ gw1, const float* __restrict__ gb1,
           const float* __restrict__ gw2, const float* __restrict__ gb2,
           float* __restrict__ out)
{
    extern __shared__ float sm[];
    float* hsm = sm;
    float* pp  = hsm + HSM_F;
    float* ys  = pp  + PP_F;
    float* b2s = ys  + YS_F;

    const int tid  = threadIdx.x;
    const int lane = tid & 31;
    const int wid  = tid >> 5;
    const int m    = wid >> 2;           // 0 drift, 1 diffusion
    const int q    = wid & 3;            // hidden-quarter
    const int j    = q * 32 + lane;      // this lane's hidden unit
    const int base = blockIdx.x * RPC;

    // ---- weights -> registers, k/j-packed as f32x2 pairs ----
    const float* W1 = m ? gw1 : dw1;
    const float* W2 = m ? gw2 : dw2;
    ull w1p[16], w2p[16];
    #pragma unroll
    for (int t = 0; t < 8; t++) {
        double2 v = *(const double2*)(W1 + j * 32 + t * 4);
        w1p[2*t]   = __double_as_longlong(v.x);
        w1p[2*t+1] = __double_as_longlong(v.y);
        double2 u = *(const double2*)(W2 + lane * 128 + q * 32 + t * 4);
        w2p[2*t]   = __double_as_longlong(u.x);
        w2p[2*t+1] = __double_as_longlong(u.y);
    }
    const float b1r = (m ? gb1 : db1)[j];
    if (tid < 64) b2s[tid] = (tid < 32) ? db2[tid] : gb2[tid - 32];

    // ---- init ys + out[0] (4 elements per thread) ----
    #pragma unroll
    for (int vv = 0; vv < 4; vv++) {
        int v = tid + vv * 256;
        float val = y0[(size_t)base * 32 + v];
        ys[v] = val;
        out[(size_t)base * 32 + v] = val;
    }
    __syncthreads();

    const float dt   = 0.01f;
    const float sqdt = __fsqrt_rn(dt);
    float* hwr = hsm + m * 4096;                       // [r][128]
    float* ppw = pp + ((m * 4 + q) * RPC) * 32 + lane; // [r]*32

    for (int s = 0; s < T_STEPS; s++) {
        // prefetch this step's noise (consumed at end of step)
        const size_t nbase = ((size_t)s * NB + base) * 32;
        float nn[4];
        #pragma unroll
        for (int vv = 0; vv < 4; vv++) nn[vv] = noise[nbase + tid + vv * 256];

        // ---- GEMM1: h[r][j] = relu(b1 + sum_k W1[j][k] y[r][k]) ----
        ull acc[RPC];
        const ull binit = (ull)__float_as_uint(b1r);   // (b1, 0)
        #pragma unroll
        for (int r = 0; r < RPC; r++) acc[r] = binit;
        #pragma unroll
        for (int k4 = 0; k4 < 8; k4++) {
            #pragma unroll
            for (int r = 0; r < RPC; r++) {
                double2 yv = *(const double2*)(ys + r * 32 + k4 * 4); // broadcast
                acc[r] = ffma2(w1p[2*k4],   __double_as_longlong(yv.x), acc[r]);
                acc[r] = ffma2(w1p[2*k4+1], __double_as_longlong(yv.y), acc[r]);
            }
        }
        #pragma unroll
        for (int r = 0; r < RPC; r++)
            hwr[r * 128 + j] = fmaxf(pair_sum(acc[r]), 0.0f);
        __syncthreads();

        // ---- GEMM2: partial[r][i=lane] = sum_{j in quarter} W2[i][j] h[r][j] ----
        ull a2[RPC];
        #pragma unroll
        for (int r = 0; r < RPC; r++) a2[r] = 0ull;
        const float* hrd = hsm + m * 4096 + q * 32;
        #pragma unroll
        for (int j4 = 0; j4 < 8; j4++) {
            #pragma unroll
            for (int r = 0; r < RPC; r++) {
                double2 hv = *(const double2*)(hrd + r * 128 + j4 * 4); // broadcast
                a2[r] = ffma2(w2p[2*j4],   __double_as_longlong(hv.x), a2[r]);
                a2[r] = ffma2(w2p[2*j4+1], __double_as_longlong(hv.y), a2[r]);
            }
        }
        #pragma unroll
        for (int r = 0; r < RPC; r++) ppw[r * 32] = pair_sum(a2[r]);
        __syncthreads();

        // ---- reduce quarters + Euler–Maruyama (4 elements per thread) ----
        #pragma unroll
        for (int vv = 0; vv < 4; vv++) {
            int v = tid + vv * 256;
            int r = v >> 5, i = v & 31;
            const float* p = pp + r * 32 + i;
            float f = p[0] + p[1024] + p[2048] + p[3072] + b2s[i];
            const float* pg = p + 4096;
            float g = pg[0] + pg[1024] + pg[2048] + pg[3072] + b2s[32 + i];
            float z = fmaf(g, sqdt * nn[vv], fmaf(f, dt, ys[v]));
            out[((size_t)(s + 1) * NB + base) * 32 + v] = z;
            ys[v] = z;   // each thread rewrites exactly the element it read
        }
        __syncthreads();
    }
}

extern "C" void kernel_launch(void* const* d_in, const int* in_sizes, int n_in,
                              void* d_out, int out_size)
{
    // metadata order: ts, y0, noise, drift_w1, drift_b1, drift_w2, drift_b2,
    //                 diff_w1, diff_b1, diff_w2, diff_b2
    const float* y0    = (const float*)d_in[1];
    const float* noise = (const float*)d_in[2];
    const float* dw1   = (const float*)d_in[3];
    const float* db1   = (const float*)d_in[4];
    const float* dw2   = (const float*)d_in[5];
    const float* db2   = (const float*)d_in[6];
    const float* gw1   = (const float*)d_in[7];
    const float* gb1   = (const float*)d_in[8];
    const float* gw2   = (const float*)d_in[9];
    const float* gb2   = (const float*)d_in[10];
    float* out = (float*)d_out;

    const size_t smem_bytes = SMEM_F * sizeof(float);  // 69,888 B
    cudaFuncSetAttribute(nsde3,
                         cudaFuncAttributeMaxDynamicSharedMemorySize,
                         (int)smem_bytes);
    nsde3<<<NCTA, 256, smem_bytes>>>(y0, noise, dw1, db1, dw2, db2,
                                     gw1, gb1, gw2, gb2, out);
}

// round 8
// speedup vs baseline: 2.3801x; 1.2758x over previous
#include <cuda_runtime.h>

#define T_STEPS 500
#define NB 4096
#define RPC 32          // rows per CTA
#define NCTA (NB / RPC) // 128

typedef unsigned long long ull;

// packed fp32x2 FMA (sm_103a FFMA2)
__device__ __forceinline__ ull ffma2(ull a, ull b, ull c) {
    ull d;
    asm("fma.rn.f32x2 %0, %1, %2, %3;" : "=l"(d) : "l"(a), "l"(b), "l"(c));
    return d;
}
__device__ __forceinline__ float pair_sum(ull p) {
    return __uint_as_float((unsigned)p) + __uint_as_float((unsigned)(p >> 32));
}
__device__ __forceinline__ ull packf2(float lo, float hi) {
    return (ull)__float_as_uint(lo) | ((ull)__float_as_uint(hi) << 32);
}

// SMEM: w1pk[2][16][128] ull (32KB), hsm[2][32][128] f (32KB),
//       pp[2][4][32][32] f (32KB), ys[32][32] f (4KB), b2s[64] f
#define SMEM_BYTES (4096*8 + (8192 + 8192 + 1024 + 64)*4)

__global__ __launch_bounds__(256, 1)
void nsde4(const float* __restrict__ y0, const float* __restrict__ noise,
           const float* __restrict__ dw1, const float* __restrict__ db1,
           const float* __restrict__ dw2, const float* __restrict__ db2,
           const float* __restrict__ gw1, const float* __restrict__ gb1,
           const float* __restrict__ gw2, const float* __restrict__ gb2,
           float* __restrict__ out)
{
    extern __shared__ char smraw[];
    ull*   w1pk = (ull*)smraw;            // [m][kp][j]  kp = k/2
    float* hsm  = (float*)(w1pk + 4096);  // [m][r][j]
    float* pp   = hsm + 8192;             // [m][q][r][i]
    float* ys   = pp  + 8192;             // [r][i]
    float* b2s  = ys  + 1024;             // [2][32]

    const int tid  = threadIdx.x;
    const int lane = tid & 31;
    const int wid  = tid >> 5;
    const int m    = wid >> 2;            // 0 drift, 1 diffusion
    const int base = blockIdx.x * RPC;

    // GEMM1 role: j-half + r-half
    const int hj  = (wid >> 1) & 1;
    const int rb1 = (wid & 1) * 16;
    const int j0  = hj * 64 + lane;
    const int j1  = j0 + 32;

    // GEMM2 role: j-quarter; lane -> 2 outputs, half-warp -> r-half
    const int q   = wid & 3;
    const int il  = lane & 15;
    const int rb2 = (lane >> 4) * 16;

    // ---- stage W1 into SMEM as k-packed f32x2 ----
    for (int idx = tid; idx < 4096; idx += 256) {
        int mm = idx >> 11, rest = idx & 2047;
        int kp = rest >> 7, j = rest & 127;
        const float* W = mm ? gw1 : dw1;
        w1pk[idx] = packf2(W[j * 32 + 2 * kp], W[j * 32 + 2 * kp + 1]);
    }
    // ---- W2 rows (i = il, il+16) for this quarter -> registers ----
    const float* W2 = m ? gw2 : dw2;
    ull w2p0[16], w2p1[16];
    #pragma unroll
    for (int t = 0; t < 8; t++) {
        double2 u0 = *(const double2*)(W2 + il * 128 + q * 32 + t * 4);
        w2p0[2*t]   = __double_as_longlong(u0.x);
        w2p0[2*t+1] = __double_as_longlong(u0.y);
        double2 u1 = *(const double2*)(W2 + (il + 16) * 128 + q * 32 + t * 4);
        w2p1[2*t]   = __double_as_longlong(u1.x);
        w2p1[2*t+1] = __double_as_longlong(u1.y);
    }
    const float* B1 = m ? gb1 : db1;
    const float b1_0 = B1[j0], b1_1 = B1[j1];
    if (tid < 64) b2s[tid] = (tid < 32) ? db2[tid] : gb2[tid - 32];

    // ---- init ys + out[0] ----
    #pragma unroll
    for (int vv = 0; vv < 4; vv++) {
        int v = tid + vv * 256;
        float val = y0[(size_t)base * 32 + v];
        ys[v] = val;
        out[(size_t)base * 32 + v] = val;
    }
    __syncthreads();

    const float dt   = 0.01f;
    const float sqdt = __fsqrt_rn(dt);
    const ull*   w1b = w1pk + m * 2048;
    const float* hq  = hsm + m * 4096 + q * 32;
    float*       ppb = pp + (m * 4 + q) * 1024;

    for (int s = 0; s < T_STEPS; s++) {
        // prefetch step noise
        const size_t nbase = ((size_t)s * NB + base) * 32;
        float nn[4];
        #pragma unroll
        for (int vv = 0; vv < 4; vv++) nn[vv] = noise[nbase + tid + vv * 256];

        // ---- GEMM1: h[r][j0/j1] over 16 rows; 1 y-load -> 4 ffma2 ----
        ull acc0[16], acc1[16];
        const ull bi0 = (ull)__float_as_uint(b1_0);
        const ull bi1 = (ull)__float_as_uint(b1_1);
        #pragma unroll
        for (int r = 0; r < 16; r++) { acc0[r] = bi0; acc1[r] = bi1; }
        #pragma unroll
        for (int k4 = 0; k4 < 8; k4++) {
            ull w00 = w1b[(2*k4)   * 128 + j0];
            ull w01 = w1b[(2*k4+1) * 128 + j0];
            ull w10 = w1b[(2*k4)   * 128 + j1];
            ull w11 = w1b[(2*k4+1) * 128 + j1];
            #pragma unroll
            for (int r = 0; r < 16; r++) {
                double2 yv = *(const double2*)(ys + (rb1 + r) * 32 + k4 * 4);
                ull ylo = __double_as_longlong(yv.x);
                ull yhi = __double_as_longlong(yv.y);
                acc0[r] = ffma2(w00, ylo, acc0[r]);
                acc0[r] = ffma2(w01, yhi, acc0[r]);
                acc1[r] = ffma2(w10, ylo, acc1[r]);
                acc1[r] = ffma2(w11, yhi, acc1[r]);
            }
        }
        #pragma unroll
        for (int r = 0; r < 16; r++) {
            hsm[m * 4096 + (rb1 + r) * 128 + j0] = fmaxf(pair_sum(acc0[r]), 0.0f);
            hsm[m * 4096 + (rb1 + r) * 128 + j1] = fmaxf(pair_sum(acc1[r]), 0.0f);
        }
        __syncthreads();

        // ---- GEMM2: partial[r][il], [r][il+16]; 1 h-load -> 4 ffma2 ----
        ull a0[16], a1[16];
        #pragma unroll
        for (int r = 0; r < 16; r++) { a0[r] = 0ull; a1[r] = 0ull; }
        #pragma unroll
        for (int j4 = 0; j4 < 8; j4++) {
            #pragma unroll
            for (int r = 0; r < 16; r++) {
                double2 hv = *(const double2*)(hq + (rb2 + r) * 128 + j4 * 4);
                ull hlo = __double_as_longlong(hv.x);
                ull hhi = __double_as_longlong(hv.y);
                a0[r] = ffma2(w2p0[2*j4],   hlo, a0[r]);
                a0[r] = ffma2(w2p0[2*j4+1], hhi, a0[r]);
                a1[r] = ffma2(w2p1[2*j4],   hlo, a1[r]);
                a1[r] = ffma2(w2p1[2*j4+1], hhi, a1[r]);
            }
        }
        #pragma unroll
        for (int r = 0; r < 16; r++) {
            ppb[(rb2 + r) * 32 + il]      = pair_sum(a0[r]);
            ppb[(rb2 + r) * 32 + il + 16] = pair_sum(a1[r]);
        }
        __syncthreads();

        // ---- reduce quarters + Euler–Maruyama (4 elements/thread) ----
        #pragma unroll
        for (int vv = 0; vv < 4; vv++) {
            int v = tid + vv * 256;
            int r = v >> 5, i = v & 31;
            const float* p = pp + r * 32 + i;
            float f = p[0] + p[1024] + p[2048] + p[3072] + b2s[i];
            const float* pg = p + 4096;
            float g = pg[0] + pg[1024] + pg[2048] + pg[3072] + b2s[32 + i];
            float z = fmaf(g, sqdt * nn[vv], fmaf(f, dt, ys[v]));
            out[((size_t)(s + 1) * NB + base) * 32 + v] = z;
            ys[v] = z;   // rewrites exactly the element it read
        }
        __syncthreads();
    }
}

extern "C" void kernel_launch(void* const* d_in, const int* in_sizes, int n_in,
                              void* d_out, int out_size)
{
    // metadata order: ts, y0, noise, drift_w1, drift_b1, drift_w2, drift_b2,
    //                 diff_w1, diff_b1, diff_w2, diff_b2
    const float* y0    = (const float*)d_in[1];
    const float* noise = (const float*)d_in[2];
    const float* dw1   = (const float*)d_in[3];
    const float* db1   = (const float*)d_in[4];
    const float* dw2   = (const float*)d_in[5];
    const float* db2   = (const float*)d_in[6];
    const float* gw1   = (const float*)d_in[7];
    const float* gb1   = (const float*)d_in[8];
    const float* gw2   = (const float*)d_in[9];
    const float* gb2   = (const float*)d_in[10];
    float* out = (float*)d_out;

    cudaFuncSetAttribute(nsde4,
                         cudaFuncAttributeMaxDynamicSharedMemorySize,
                         SMEM_BYTES);
    nsde4<<<NCTA, 256, SMEM_BYTES>>>(y0, noise, dw1, db1, dw2, db2,
                                     gw1, gb1, gw2, gb2, out);
}